// round 14
// baseline (speedup 1.0000x reference)
#include <cuda_runtime.h>

// FeedForwardQuantum: out = relu(cos(x+theta) @ W1 + b1) @ W2 + b2
// x: [524288, 8] fp32, W1: [8,32], W2: [32,8].
// Plateau analysis: all 160 weight loads/chunk on the constant port (LDC
// structural floor 8 cyc) ~= the whole 32k-cycle runtime -> LDC co-bottleneck.
// R6: port-split weights: W1+b1 via __constant__ (LDC), W2+b2 via __shared__
// (LDS.128 broadcast, floor 2). Drop manual cos range reduction (__cosf direct,
// |x+theta|<~10 -> MUFU error ~1e-6 << 1e-3 gate). R4 float2 carriage (best).

#define EDIM 8
#define FDIM 32
#define RPT 2      // rows per thread (one f32x2 pair)
#define BLOCK 128

struct CW {
    float4 w1c[FDIM][2];  // [f]: w1[e0..3][f], w1[e4..7][f] (transposed)
    float  b1[FDIM];
};

__constant__ CW c_w;     // W1 via constant port
__device__   CW g_s;     // scratch filled by prep kernel, memcpy'd into c_w

// packed f32x2 ops (float2 carriage; ptxas coalesces the pack movs)
__device__ __forceinline__ float2 ffma2(float2 a, float2 b, float2 c) {
    float2 d;
    asm("{\n\t"
        ".reg .b64 ra, rb, rc, rd;\n\t"
        "mov.b64 ra, {%2, %3};\n\t"
        "mov.b64 rb, {%4, %5};\n\t"
        "mov.b64 rc, {%6, %7};\n\t"
        "fma.rn.f32x2 rd, ra, rb, rc;\n\t"
        "mov.b64 {%0, %1}, rd;\n\t"
        "}"
        : "=f"(d.x), "=f"(d.y)
        : "f"(a.x), "f"(a.y), "f"(b.x), "f"(b.y), "f"(c.x), "f"(c.y));
    return d;
}
__device__ __forceinline__ float2 fmul2(float2 a, float2 b) {
    float2 d;
    asm("{\n\t"
        ".reg .b64 ra, rb, rd;\n\t"
        "mov.b64 ra, {%2, %3};\n\t"
        "mov.b64 rb, {%4, %5};\n\t"
        "mul.rn.f32x2 rd, ra, rb;\n\t"
        "mov.b64 {%0, %1}, rd;\n\t"
        "}"
        : "=f"(d.x), "=f"(d.y)
        : "f"(a.x), "f"(a.y), "f"(b.x), "f"(b.y));
    return d;
}
__device__ __forceinline__ float2 fadd2(float2 a, float2 b) {
    float2 d;
    asm("{\n\t"
        ".reg .b64 ra, rb, rd;\n\t"
        "mov.b64 ra, {%2, %3};\n\t"
        "mov.b64 rb, {%4, %5};\n\t"
        "add.rn.f32x2 rd, ra, rb;\n\t"
        "mov.b64 {%0, %1}, rd;\n\t"
        "}"
        : "=f"(d.x), "=f"(d.y)
        : "f"(a.x), "f"(a.y), "f"(b.x), "f"(b.y));
    return d;
}
__device__ __forceinline__ float2 dup2(float v) { return make_float2(v, v); }

__global__ void ffq_prep(const float* __restrict__ w1, const float* __restrict__ b1)
{
    int f = threadIdx.x;
    if (f < FDIM) {
        g_s.w1c[f][0] = make_float4(w1[0 * FDIM + f], w1[1 * FDIM + f],
                                    w1[2 * FDIM + f], w1[3 * FDIM + f]);
        g_s.w1c[f][1] = make_float4(w1[4 * FDIM + f], w1[5 * FDIM + f],
                                    w1[6 * FDIM + f], w1[7 * FDIM + f]);
        g_s.b1[f] = b1[f];
    }
}

__global__ void __launch_bounds__(BLOCK)
ffq_kernel(const float* __restrict__ x, const float* __restrict__ theta,
           const float* __restrict__ w2g, const float* __restrict__ b2g,
           float* __restrict__ out, long long nrows)
{
    // W2 + b2 in shared (LDS port), W1 + b1 in constant (LDC port)
    __shared__ float4 s_w2[FDIM][2];   // [f]: w2[f][e0..3], w2[f][e4..7]
    __shared__ float  s_b2[EDIM];

    const int t = threadIdx.x;
    if (t < FDIM * 2) s_w2[t >> 1][t & 1] = reinterpret_cast<const float4*>(w2g)[t];
    if (t < EDIM)     s_b2[t] = b2g[t];
    __syncthreads();

    const long long idx  = (long long)blockIdx.x * BLOCK + t;
    const long long row0 = idx * RPT;
    if (row0 >= nrows) return;

    float th[EDIM];
#pragma unroll
    for (int e = 0; e < EDIM; e++) th[e] = __ldg(theta + e);

    if (row0 + RPT <= nrows) {
        // ---- fast path: 2 rows; q[e] = (cos row0, cos row1) ----
        const float4* xp = reinterpret_cast<const float4*>(x + row0 * EDIM);
        float4 a0 = xp[0], a1 = xp[1];   // row 0
        float4 b0 = xp[2], b1v = xp[3];  // row 1

        float2 q[EDIM];
        q[0] = make_float2(__cosf(a0.x + th[0]), __cosf(b0.x + th[0]));
        q[1] = make_float2(__cosf(a0.y + th[1]), __cosf(b0.y + th[1]));
        q[2] = make_float2(__cosf(a0.z + th[2]), __cosf(b0.z + th[2]));
        q[3] = make_float2(__cosf(a0.w + th[3]), __cosf(b0.w + th[3]));
        q[4] = make_float2(__cosf(a1.x + th[4]), __cosf(b1v.x + th[4]));
        q[5] = make_float2(__cosf(a1.y + th[5]), __cosf(b1v.y + th[5]));
        q[6] = make_float2(__cosf(a1.z + th[6]), __cosf(b1v.z + th[6]));
        q[7] = make_float2(__cosf(a1.w + th[7]), __cosf(b1v.w + th[7]));

        float2 acc[EDIM];
#pragma unroll
        for (int e = 0; e < EDIM; e++) acc[e] = dup2(s_b2[e]);

#pragma unroll
        for (int f = 0; f < FDIM; f++) {
            float4 wa = c_w.w1c[f][0];   // LDC.128
            float4 wb = c_w.w1c[f][1];   // LDC.128
            float  bf = c_w.b1[f];

            // 2-way split chain (depth 4 + join)
            float2 ha = ffma2(q[0], dup2(wa.x), dup2(bf));
            float2 hb = fmul2(q[1], dup2(wa.y));
            ha = ffma2(q[2], dup2(wa.z), ha);
            hb = ffma2(q[3], dup2(wa.w), hb);
            ha = ffma2(q[4], dup2(wb.x), ha);
            hb = ffma2(q[5], dup2(wb.y), hb);
            ha = ffma2(q[6], dup2(wb.z), ha);
            hb = ffma2(q[7], dup2(wb.w), hb);
            float2 h = fadd2(ha, hb);
            h.x = fmaxf(h.x, 0.0f);
            h.y = fmaxf(h.y, 0.0f);

            float4 va = s_w2[f][0];      // LDS.128 (broadcast)
            float4 vb = s_w2[f][1];      // LDS.128 (broadcast)
            acc[0] = ffma2(h, dup2(va.x), acc[0]);
            acc[1] = ffma2(h, dup2(va.y), acc[1]);
            acc[2] = ffma2(h, dup2(va.z), acc[2]);
            acc[3] = ffma2(h, dup2(va.w), acc[3]);
            acc[4] = ffma2(h, dup2(vb.x), acc[4]);
            acc[5] = ffma2(h, dup2(vb.y), acc[5]);
            acc[6] = ffma2(h, dup2(vb.z), acc[6]);
            acc[7] = ffma2(h, dup2(vb.w), acc[7]);
        }

        float4* op = reinterpret_cast<float4*>(out + row0 * EDIM);
        op[0] = make_float4(acc[0].x, acc[1].x, acc[2].x, acc[3].x);
        op[1] = make_float4(acc[4].x, acc[5].x, acc[6].x, acc[7].x);
        op[2] = make_float4(acc[0].y, acc[1].y, acc[2].y, acc[3].y);
        op[3] = make_float4(acc[4].y, acc[5].y, acc[6].y, acc[7].y);
    } else {
        // ---- tail: scalar per-row fallback ----
        for (long long r = row0; r < nrows; r++) {
            float q[EDIM];
#pragma unroll
            for (int e = 0; e < EDIM; e++) q[e] = __cosf(x[r * EDIM + e] + th[e]);
            float o[EDIM];
#pragma unroll
            for (int e = 0; e < EDIM; e++) o[e] = s_b2[e];
            for (int f = 0; f < FDIM; f++) {
                float h = c_w.b1[f];
                const float* w1c = reinterpret_cast<const float*>(&c_w.w1c[f][0]);
                const float* w2r = reinterpret_cast<const float*>(&s_w2[f][0]);
#pragma unroll
                for (int e = 0; e < EDIM; e++) h = fmaf(q[e], w1c[e], h);
                h = fmaxf(h, 0.0f);
#pragma unroll
                for (int e = 0; e < EDIM; e++) o[e] = fmaf(h, w2r[e], o[e]);
            }
#pragma unroll
            for (int e = 0; e < EDIM; e++) out[r * EDIM + e] = o[e];
        }
    }
}

extern "C" void kernel_launch(void* const* d_in, const int* in_sizes, int n_in,
                              void* d_out, int out_size) {
    const float* x     = (const float*)d_in[0];
    const float* theta = (const float*)d_in[1];
    const float* w1    = (const float*)d_in[2];
    const float* b1    = (const float*)d_in[3];
    const float* w2    = (const float*)d_in[4];
    const float* b2    = (const float*)d_in[5];
    float* out = (float*)d_out;

    long long nrows = (long long)in_sizes[0] / EDIM;
    long long nthreads = (nrows + RPT - 1) / RPT;
    int blocks = (int)((nthreads + BLOCK - 1) / BLOCK);

    // transpose W1 into device scratch, then graph-legal D2D into __constant__
    ffq_prep<<<1, 64>>>(w1, b1);
    void *c_ptr = nullptr, *s_ptr = nullptr;
    cudaGetSymbolAddress(&c_ptr, c_w);
    cudaGetSymbolAddress(&s_ptr, g_s);
    cudaMemcpyAsync(c_ptr, s_ptr, sizeof(CW), cudaMemcpyDeviceToDevice, 0);

    ffq_kernel<<<blocks, BLOCK>>>(x, theta, w2, b2, out, nrows);
}